// round 7
// baseline (speedup 1.0000x reference)
#include <cuda_runtime.h>

#define BATCH 8
#define CD 512
#define NB 256   // coarse blocks per image (16x16 of 4x4)
#define HW 4096

// ---------------- scratch (device globals; no allocation allowed) ----------
__device__ float g_xavg[BATCH * CD * NB];   // (b, c, n)  K-major for GEMM A
__device__ float g_xrow[BATCH * CD * NB];   // (b, c, n)
__device__ float g_Q[BATCH * NB * CD];      // (b, n, c)
__device__ float g_K[BATCH * NB * CD];
__device__ float g_V[BATCH * NB * CD];      // Vsum
__device__ float g_S[BATCH * NB * NB];      // scores / softmax in place
__device__ float g_OS[BATCH * NB * CD];     // out_small

// ---------------- 1) fused reduce: block means + flat row-segment sums -----
// one block per (b,c) plane of 64x64. Reads x exactly once.
__global__ __launch_bounds__(256) void reduce_kernel(const float* __restrict__ x) {
    __shared__ float chunk[1024];   // sum of each 4-float chunk; f = h*16 + w/4
    int plane = blockIdx.x;         // b*512 + c
    const float4* xp = reinterpret_cast<const float4*>(x) + (size_t)plane * 1024;
    int t = threadIdx.x;
#pragma unroll
    for (int i = 0; i < 4; i++) {
        float4 v = xp[t + i * 256];
        chunk[t + i * 256] = v.x + v.y + v.z + v.w;
    }
    __syncthreads();
    // row-segment g = t: chunks 4t..4t+3 (same image row, 16 consecutive w)
    float rs = chunk[4 * t] + chunk[4 * t + 1] + chunk[4 * t + 2] + chunk[4 * t + 3];
    // block n = t: bh = t>>4, bw = t&15 -> chunks bh*64 + bw + {0,16,32,48}
    int base = ((t >> 4) << 6) + (t & 15);
    float bs = chunk[base] + chunk[base + 16] + chunk[base + 32] + chunk[base + 48];
    size_t o = (size_t)plane * NB + t;
    g_xrow[o] = rs;             // raw sum (V path)
    g_xavg[o] = bs * 0.0625f;   // mean over 16
}

// ---------------- 2) fused Q/K/Vsum GEMM ------------------------------------
// C[m,o] = sum_c A_T[c,m] * W[o,c] + bias[o]*bscale ; per batch M=256,N=512,K=512
__global__ __launch_bounds__(256) void gemm_qkv_kernel(
    const float* __restrict__ Wq, const float* __restrict__ bq,
    const float* __restrict__ Wk, const float* __restrict__ bk,
    const float* __restrict__ Wv, const float* __restrict__ bv) {
    int z = blockIdx.z;
    int b = z / 3, which = z - 3 * b;
    const float* A = (which == 2 ? g_xrow : g_xavg) + (size_t)b * CD * NB;
    const float* W;
    const float* bias;
    float* out;
    float bscale;
    if (which == 0)      { W = Wq; bias = bq; out = g_Q; bscale = 1.f; }
    else if (which == 1) { W = Wk; bias = bk; out = g_K; bscale = 1.f; }
    else                 { W = Wv; bias = bv; out = g_V; bscale = 16.f; }
    out += (size_t)b * NB * CD;

    int n0 = blockIdx.x * 128, m0 = blockIdx.y * 128;
    __shared__ float As[8][128];
    __shared__ float Bs[8][128];
    int t = threadIdx.x;
    int tx = t & 15, ty = t >> 4;
    int a_kk = t >> 5, a_mm = (t & 31) << 2;     // A tile load coords
    int b_nn = t >> 1, b_h = (t & 1) << 2;       // B tile load coords
    float acc[8][8] = {};

    for (int k0 = 0; k0 < CD; k0 += 8) {
        float4 av = *reinterpret_cast<const float4*>(&A[(size_t)(k0 + a_kk) * NB + m0 + a_mm]);
        float4 wv = *reinterpret_cast<const float4*>(&W[(size_t)(n0 + b_nn) * CD + k0 + b_h]);
        *reinterpret_cast<float4*>(&As[a_kk][a_mm]) = av;
        Bs[b_h + 0][b_nn] = wv.x;
        Bs[b_h + 1][b_nn] = wv.y;
        Bs[b_h + 2][b_nn] = wv.z;
        Bs[b_h + 3][b_nn] = wv.w;
        __syncthreads();
#pragma unroll
        for (int kk = 0; kk < 8; kk++) {
            float ra[8], rb[8];
#pragma unroll
            for (int i = 0; i < 8; i++) ra[i] = As[kk][ty * 8 + i];
#pragma unroll
            for (int j = 0; j < 8; j++) rb[j] = Bs[kk][tx * 8 + j];
#pragma unroll
            for (int i = 0; i < 8; i++)
#pragma unroll
                for (int j = 0; j < 8; j++) acc[i][j] += ra[i] * rb[j];
        }
        __syncthreads();
    }
#pragma unroll
    for (int i = 0; i < 8; i++) {
        int row = m0 + ty * 8 + i;
#pragma unroll
        for (int j = 0; j < 8; j += 4) {
            int col = n0 + tx * 8 + j;
            float4 v;
            v.x = acc[i][j]     + bias[col]     * bscale;
            v.y = acc[i][j + 1] + bias[col + 1] * bscale;
            v.z = acc[i][j + 2] + bias[col + 2] * bscale;
            v.w = acc[i][j + 3] + bias[col + 3] * bscale;
            *reinterpret_cast<float4*>(&out[(size_t)row * CD + col]) = v;
        }
    }
}

// ---------------- 3) scores: S = Q K^T / sqrt(C) ----------------------------
__global__ __launch_bounds__(256) void scores_kernel() {
    int b = blockIdx.z;
    int n0 = blockIdx.x * 64, m0 = blockIdx.y * 64;
    const float* Qb = g_Q + (size_t)b * NB * CD;
    const float* Kb = g_K + (size_t)b * NB * CD;
    __shared__ float Qs[16][68];
    __shared__ float Ks[16][68];
    int t = threadIdx.x;
    int row = t >> 2, kq = (t & 3) << 2;
    int tx = t & 15, ty = t >> 4;
    float acc[4][4] = {};

    for (int k0 = 0; k0 < CD; k0 += 16) {
        float4 q4 = *reinterpret_cast<const float4*>(&Qb[(size_t)(m0 + row) * CD + k0 + kq]);
        float4 k4 = *reinterpret_cast<const float4*>(&Kb[(size_t)(n0 + row) * CD + k0 + kq]);
        Qs[kq + 0][row] = q4.x; Qs[kq + 1][row] = q4.y;
        Qs[kq + 2][row] = q4.z; Qs[kq + 3][row] = q4.w;
        Ks[kq + 0][row] = k4.x; Ks[kq + 1][row] = k4.y;
        Ks[kq + 2][row] = k4.z; Ks[kq + 3][row] = k4.w;
        __syncthreads();
#pragma unroll
        for (int kk = 0; kk < 16; kk++) {
            float rq[4], rk[4];
#pragma unroll
            for (int i = 0; i < 4; i++) rq[i] = Qs[kk][ty * 4 + i];
#pragma unroll
            for (int j = 0; j < 4; j++) rk[j] = Ks[kk][tx * 4 + j];
#pragma unroll
            for (int i = 0; i < 4; i++)
#pragma unroll
                for (int j = 0; j < 4; j++) acc[i][j] += rq[i] * rk[j];
        }
        __syncthreads();
    }
    const float scale = 0.044194173824159216f;  // 1/sqrt(512)
    float* Sb = g_S + (size_t)b * NB * NB;
#pragma unroll
    for (int i = 0; i < 4; i++) {
        int r = m0 + ty * 4 + i;
        float4 v;
        v.x = acc[i][0] * scale; v.y = acc[i][1] * scale;
        v.z = acc[i][2] * scale; v.w = acc[i][3] * scale;
        *reinterpret_cast<float4*>(&Sb[(size_t)r * NB + n0 + tx * 4]) = v;
    }
}

// ---------------- 4) row softmax in place (one warp per row) ----------------
__global__ __launch_bounds__(256) void softmax_kernel() {
    int row = blockIdx.x * 8 + (threadIdx.x >> 5);
    int lane = threadIdx.x & 31;
    float* r = g_S + (size_t)row * NB;
    float v[8];
    float mx = -1e30f;
#pragma unroll
    for (int i = 0; i < 8; i++) {
        v[i] = r[lane + i * 32];
        mx = fmaxf(mx, v[i]);
    }
#pragma unroll
    for (int o = 16; o > 0; o >>= 1) mx = fmaxf(mx, __shfl_xor_sync(0xffffffffu, mx, o));
    float s = 0.f;
#pragma unroll
    for (int i = 0; i < 8; i++) { v[i] = __expf(v[i] - mx); s += v[i]; }
#pragma unroll
    for (int o = 16; o > 0; o >>= 1) s += __shfl_xor_sync(0xffffffffu, s, o);
    float inv = 1.0f / s;
#pragma unroll
    for (int i = 0; i < 8; i++) r[lane + i * 32] = v[i] * inv;
}

// ---------------- 5) out_small = A @ Vsum ------------------------------------
__global__ __launch_bounds__(256) void gemm_av_kernel() {
    int b = blockIdx.z;
    const float* A = g_S + (size_t)b * NB * NB;
    const float* Bm = g_V + (size_t)b * NB * CD;
    float* out = g_OS + (size_t)b * NB * CD;
    int n0 = blockIdx.x * 128, m0 = blockIdx.y * 128;
    __shared__ float As[8][128];
    __shared__ float Bs[8][128];
    int t = threadIdx.x;
    int tx = t & 15, ty = t >> 4;
    int a_mm = t >> 1, a_h = (t & 1) << 2;
    int b_kk = t >> 5, b_nn = (t & 31) << 2;
    float acc[8][8] = {};

    for (int k0 = 0; k0 < NB; k0 += 8) {
        float4 a4 = *reinterpret_cast<const float4*>(&A[(size_t)(m0 + a_mm) * NB + k0 + a_h]);
        float4 b4 = *reinterpret_cast<const float4*>(&Bm[(size_t)(k0 + b_kk) * CD + n0 + b_nn]);
        As[a_h + 0][a_mm] = a4.x;
        As[a_h + 1][a_mm] = a4.y;
        As[a_h + 2][a_mm] = a4.z;
        As[a_h + 3][a_mm] = a4.w;
        *reinterpret_cast<float4*>(&Bs[b_kk][b_nn]) = b4;
        __syncthreads();
#pragma unroll
        for (int kk = 0; kk < 8; kk++) {
            float ra[8], rb[8];
#pragma unroll
            for (int i = 0; i < 8; i++) ra[i] = As[kk][ty * 8 + i];
#pragma unroll
            for (int j = 0; j < 8; j++) rb[j] = Bs[kk][tx * 8 + j];
#pragma unroll
            for (int i = 0; i < 8; i++)
#pragma unroll
                for (int j = 0; j < 8; j++) acc[i][j] += ra[i] * rb[j];
        }
        __syncthreads();
    }
#pragma unroll
    for (int i = 0; i < 8; i++) {
        int row = m0 + ty * 8 + i;
#pragma unroll
        for (int j = 0; j < 8; j += 4) {
            int col = n0 + tx * 8 + j;
            float4 v;
            v.x = acc[i][j];
            v.y = acc[i][j + 1];
            v.z = acc[i][j + 2];
            v.w = acc[i][j + 3];
            *reinterpret_cast<float4*>(&out[(size_t)row * CD + col]) = v;
        }
    }
}

// ---------------- 6) scatter: broadcast each block row to 16 flat pixels ----
__global__ __launch_bounds__(1024) void scatter_kernel(float* __restrict__ out) {
    unsigned idx = blockIdx.x * 1024u + threadIdx.x;   // b,c,h,w flat
    unsigned b = idx >> 21;           // 512*4096 = 2^21
    unsigned rem = idx & 0x1FFFFFu;
    unsigned c = rem >> 12;           // /4096
    unsigned p = rem & 4095u;         // flat pixel
    unsigned n = p >> 4;              // flat group
    out[idx] = g_OS[((((b << 8) + n) << 9)) + c];
}

extern "C" void kernel_launch(void* const* d_in, const int* in_sizes, int n_in,
                              void* d_out, int out_size) {
    const float* x  = (const float*)d_in[0];
    const float* Wq = (const float*)d_in[1];
    const float* bq = (const float*)d_in[2];
    const float* Wk = (const float*)d_in[3];
    const float* bk = (const float*)d_in[4];
    const float* Wv = (const float*)d_in[5];
    const float* bv = (const float*)d_in[6];
    float* out = (float*)d_out;

    reduce_kernel<<<BATCH * CD, 256>>>(x);
    gemm_qkv_kernel<<<dim3(4, 2, BATCH * 3), 256>>>(Wq, bq, Wk, bk, Wv, bv);
    scores_kernel<<<dim3(4, 4, BATCH), 256>>>();
    softmax_kernel<<<BATCH * NB / 8, 256>>>();
    gemm_av_kernel<<<dim3(4, 2, BATCH), 256>>>();
    scatter_kernel<<<16384, 1024>>>(out);
}

// round 8
// speedup vs baseline: 1.0008x; 1.0008x over previous
#include <cuda_runtime.h>

#define BATCH 8
#define CD 512
#define NB 256   // coarse blocks per image (16x16 of 4x4)
#define HW 4096

// ---------------- scratch (device globals; no allocation allowed) ----------
__device__ float g_xavg[BATCH * CD * NB];   // (b, c, n)  K-major for GEMM A
__device__ float g_xrow[BATCH * CD * NB];   // (b, c, n)
__device__ float g_Q[BATCH * NB * CD];      // (b, n, c)
__device__ float g_K[BATCH * NB * CD];
__device__ float g_V[BATCH * NB * CD];      // Vsum
__device__ float g_S[BATCH * NB * NB];      // scores / softmax in place
__device__ float g_OS[BATCH * NB * CD];     // out_small

// ---------------- 1) fused reduce: block means + flat row-segment sums -----
// one block per (b,c) plane of 64x64. Reads x exactly once.
__global__ __launch_bounds__(256) void reduce_kernel(const float* __restrict__ x) {
    __shared__ float chunk[1024];   // sum of each 4-float chunk; f = h*16 + w/4
    int plane = blockIdx.x;         // b*512 + c
    const float4* xp = reinterpret_cast<const float4*>(x) + (size_t)plane * 1024;
    int t = threadIdx.x;
#pragma unroll
    for (int i = 0; i < 4; i++) {
        float4 v = xp[t + i * 256];
        chunk[t + i * 256] = v.x + v.y + v.z + v.w;
    }
    __syncthreads();
    // row-segment g = t: chunks 4t..4t+3 (same image row, 16 consecutive w)
    float rs = chunk[4 * t] + chunk[4 * t + 1] + chunk[4 * t + 2] + chunk[4 * t + 3];
    // block n = t: bh = t>>4, bw = t&15 -> chunks bh*64 + bw + {0,16,32,48}
    int base = ((t >> 4) << 6) + (t & 15);
    float bs = chunk[base] + chunk[base + 16] + chunk[base + 32] + chunk[base + 48];
    size_t o = (size_t)plane * NB + t;
    g_xrow[o] = rs;             // raw sum (V path)
    g_xavg[o] = bs * 0.0625f;   // mean over 16
}

// ---------------- 2) fused Q/K/Vsum GEMM ------------------------------------
// C[m,o] = sum_c A_T[c,m] * W[o,c] + bias[o]*bscale ; per batch M=256,N=512,K=512
__global__ __launch_bounds__(256) void gemm_qkv_kernel(
    const float* __restrict__ Wq, const float* __restrict__ bq,
    const float* __restrict__ Wk, const float* __restrict__ bk,
    const float* __restrict__ Wv, const float* __restrict__ bv) {
    int z = blockIdx.z;
    int b = z / 3, which = z - 3 * b;
    const float* A = (which == 2 ? g_xrow : g_xavg) + (size_t)b * CD * NB;
    const float* W;
    const float* bias;
    float* out;
    float bscale;
    if (which == 0)      { W = Wq; bias = bq; out = g_Q; bscale = 1.f; }
    else if (which == 1) { W = Wk; bias = bk; out = g_K; bscale = 1.f; }
    else                 { W = Wv; bias = bv; out = g_V; bscale = 16.f; }
    out += (size_t)b * NB * CD;

    int n0 = blockIdx.x * 128, m0 = blockIdx.y * 128;
    __shared__ float As[8][128];
    __shared__ float Bs[8][128];
    int t = threadIdx.x;
    int tx = t & 15, ty = t >> 4;
    int a_kk = t >> 5, a_mm = (t & 31) << 2;     // A tile load coords
    int b_nn = t >> 1, b_h = (t & 1) << 2;       // B tile load coords
    float acc[8][8] = {};

    for (int k0 = 0; k0 < CD; k0 += 8) {
        float4 av = *reinterpret_cast<const float4*>(&A[(size_t)(k0 + a_kk) * NB + m0 + a_mm]);
        float4 wv = *reinterpret_cast<const float4*>(&W[(size_t)(n0 + b_nn) * CD + k0 + b_h]);
        *reinterpret_cast<float4*>(&As[a_kk][a_mm]) = av;
        Bs[b_h + 0][b_nn] = wv.x;
        Bs[b_h + 1][b_nn] = wv.y;
        Bs[b_h + 2][b_nn] = wv.z;
        Bs[b_h + 3][b_nn] = wv.w;
        __syncthreads();
#pragma unroll
        for (int kk = 0; kk < 8; kk++) {
            float ra[8], rb[8];
#pragma unroll
            for (int i = 0; i < 8; i++) ra[i] = As[kk][ty * 8 + i];
#pragma unroll
            for (int j = 0; j < 8; j++) rb[j] = Bs[kk][tx * 8 + j];
#pragma unroll
            for (int i = 0; i < 8; i++)
#pragma unroll
                for (int j = 0; j < 8; j++) acc[i][j] += ra[i] * rb[j];
        }
        __syncthreads();
    }
#pragma unroll
    for (int i = 0; i < 8; i++) {
        int row = m0 + ty * 8 + i;
#pragma unroll
        for (int j = 0; j < 8; j += 4) {
            int col = n0 + tx * 8 + j;
            float4 v;
            v.x = acc[i][j]     + bias[col]     * bscale;
            v.y = acc[i][j + 1] + bias[col + 1] * bscale;
            v.z = acc[i][j + 2] + bias[col + 2] * bscale;
            v.w = acc[i][j + 3] + bias[col + 3] * bscale;
            *reinterpret_cast<float4*>(&out[(size_t)row * CD + col]) = v;
        }
    }
}

// ---------------- 3) scores: S = Q K^T / sqrt(C) ----------------------------
__global__ __launch_bounds__(256) void scores_kernel() {
    int b = blockIdx.z;
    int n0 = blockIdx.x * 64, m0 = blockIdx.y * 64;
    const float* Qb = g_Q + (size_t)b * NB * CD;
    const float* Kb = g_K + (size_t)b * NB * CD;
    __shared__ float Qs[16][68];
    __shared__ float Ks[16][68];
    int t = threadIdx.x;
    int row = t >> 2, kq = (t & 3) << 2;
    int tx = t & 15, ty = t >> 4;
    float acc[4][4] = {};

    for (int k0 = 0; k0 < CD; k0 += 16) {
        float4 q4 = *reinterpret_cast<const float4*>(&Qb[(size_t)(m0 + row) * CD + k0 + kq]);
        float4 k4 = *reinterpret_cast<const float4*>(&Kb[(size_t)(n0 + row) * CD + k0 + kq]);
        Qs[kq + 0][row] = q4.x; Qs[kq + 1][row] = q4.y;
        Qs[kq + 2][row] = q4.z; Qs[kq + 3][row] = q4.w;
        Ks[kq + 0][row] = k4.x; Ks[kq + 1][row] = k4.y;
        Ks[kq + 2][row] = k4.z; Ks[kq + 3][row] = k4.w;
        __syncthreads();
#pragma unroll
        for (int kk = 0; kk < 16; kk++) {
            float rq[4], rk[4];
#pragma unroll
            for (int i = 0; i < 4; i++) rq[i] = Qs[kk][ty * 4 + i];
#pragma unroll
            for (int j = 0; j < 4; j++) rk[j] = Ks[kk][tx * 4 + j];
#pragma unroll
            for (int i = 0; i < 4; i++)
#pragma unroll
                for (int j = 0; j < 4; j++) acc[i][j] += rq[i] * rk[j];
        }
        __syncthreads();
    }
    const float scale = 0.044194173824159216f;  // 1/sqrt(512)
    float* Sb = g_S + (size_t)b * NB * NB;
#pragma unroll
    for (int i = 0; i < 4; i++) {
        int r = m0 + ty * 4 + i;
        float4 v;
        v.x = acc[i][0] * scale; v.y = acc[i][1] * scale;
        v.z = acc[i][2] * scale; v.w = acc[i][3] * scale;
        *reinterpret_cast<float4*>(&Sb[(size_t)r * NB + n0 + tx * 4]) = v;
    }
}

// ---------------- 4) row softmax in place (one warp per row) ----------------
__global__ __launch_bounds__(256) void softmax_kernel() {
    int row = blockIdx.x * 8 + (threadIdx.x >> 5);
    int lane = threadIdx.x & 31;
    float* r = g_S + (size_t)row * NB;
    float v[8];
    float mx = -1e30f;
#pragma unroll
    for (int i = 0; i < 8; i++) {
        v[i] = r[lane + i * 32];
        mx = fmaxf(mx, v[i]);
    }
#pragma unroll
    for (int o = 16; o > 0; o >>= 1) mx = fmaxf(mx, __shfl_xor_sync(0xffffffffu, mx, o));
    float s = 0.f;
#pragma unroll
    for (int i = 0; i < 8; i++) { v[i] = __expf(v[i] - mx); s += v[i]; }
#pragma unroll
    for (int o = 16; o > 0; o >>= 1) s += __shfl_xor_sync(0xffffffffu, s, o);
    float inv = 1.0f / s;
#pragma unroll
    for (int i = 0; i < 8; i++) r[lane + i * 32] = v[i] * inv;
}

// ---------------- 5) out_small = A @ Vsum ------------------------------------
__global__ __launch_bounds__(256) void gemm_av_kernel() {
    int b = blockIdx.z;
    const float* A = g_S + (size_t)b * NB * NB;
    const float* Bm = g_V + (size_t)b * NB * CD;
    float* out = g_OS + (size_t)b * NB * CD;
    int n0 = blockIdx.x * 128, m0 = blockIdx.y * 128;
    __shared__ float As[8][128];
    __shared__ float Bs[8][128];
    int t = threadIdx.x;
    int tx = t & 15, ty = t >> 4;
    int a_mm = t >> 1, a_h = (t & 1) << 2;
    int b_kk = t >> 5, b_nn = (t & 31) << 2;
    float acc[8][8] = {};

    for (int k0 = 0; k0 < NB; k0 += 8) {
        float4 a4 = *reinterpret_cast<const float4*>(&A[(size_t)(m0 + a_mm) * NB + k0 + a_h]);
        float4 b4 = *reinterpret_cast<const float4*>(&Bm[(size_t)(k0 + b_kk) * CD + n0 + b_nn]);
        As[a_h + 0][a_mm] = a4.x;
        As[a_h + 1][a_mm] = a4.y;
        As[a_h + 2][a_mm] = a4.z;
        As[a_h + 3][a_mm] = a4.w;
        *reinterpret_cast<float4*>(&Bs[b_kk][b_nn]) = b4;
        __syncthreads();
#pragma unroll
        for (int kk = 0; kk < 8; kk++) {
            float ra[8], rb[8];
#pragma unroll
            for (int i = 0; i < 8; i++) ra[i] = As[kk][ty * 8 + i];
#pragma unroll
            for (int j = 0; j < 8; j++) rb[j] = Bs[kk][tx * 8 + j];
#pragma unroll
            for (int i = 0; i < 8; i++)
#pragma unroll
                for (int j = 0; j < 8; j++) acc[i][j] += ra[i] * rb[j];
        }
        __syncthreads();
    }
#pragma unroll
    for (int i = 0; i < 8; i++) {
        int row = m0 + ty * 8 + i;
#pragma unroll
        for (int j = 0; j < 8; j += 4) {
            int col = n0 + tx * 8 + j;
            float4 v;
            v.x = acc[i][j];
            v.y = acc[i][j + 1];
            v.z = acc[i][j + 2];
            v.w = acc[i][j + 3];
            *reinterpret_cast<float4*>(&out[(size_t)row * CD + col]) = v;
        }
    }
}

// ---------------- 6) scatter: broadcast each block row to 16 flat pixels ----
__global__ __launch_bounds__(1024) void scatter_kernel(float* __restrict__ out) {
    unsigned idx = blockIdx.x * 1024u + threadIdx.x;   // b,c,h,w flat
    unsigned b = idx >> 21;           // 512*4096 = 2^21
    unsigned rem = idx & 0x1FFFFFu;
    unsigned c = rem >> 12;           // /4096
    unsigned p = rem & 4095u;         // flat pixel
    unsigned n = p >> 4;              // flat group
    out[idx] = g_OS[((((b << 8) + n) << 9)) + c];
}

extern "C" void kernel_launch(void* const* d_in, const int* in_sizes, int n_in,
                              void* d_out, int out_size) {
    const float* x  = (const float*)d_in[0];
    const float* Wq = (const float*)d_in[1];
    const float* bq = (const float*)d_in[2];
    const float* Wk = (const float*)d_in[3];
    const float* bk = (const float*)d_in[4];
    const float* Wv = (const float*)d_in[5];
    const float* bv = (const float*)d_in[6];
    float* out = (float*)d_out;

    reduce_kernel<<<BATCH * CD, 256>>>(x);
    gemm_qkv_kernel<<<dim3(4, 2, BATCH * 3), 256>>>(Wq, bq, Wk, bk, Wv, bv);
    scores_kernel<<<dim3(4, 4, BATCH), 256>>>();
    softmax_kernel<<<BATCH * NB / 8, 256>>>();
    gemm_av_kernel<<<dim3(4, 2, BATCH), 256>>>();
    scatter_kernel<<<16384, 1024>>>(out);
}

// round 9
// speedup vs baseline: 1.0064x; 1.0056x over previous
#include <cuda_runtime.h>

#define BATCH 8
#define CD 512
#define NB 256   // coarse blocks per image (16x16 of 4x4)
#define HW 4096

// ---------------- scratch (device globals; no allocation allowed) ----------
__device__ float g_xavg[BATCH * CD * NB];   // (b, c, n)  K-major for GEMM A
__device__ float g_xrow[BATCH * CD * NB];   // (b, c, n)
__device__ float g_Q[BATCH * NB * CD];      // (b, n, c)
__device__ float g_K[BATCH * NB * CD];
__device__ float g_V[BATCH * NB * CD];      // Vsum
__device__ float g_S[BATCH * NB * NB];      // scores / softmax in place
__device__ float g_OS[BATCH * NB * CD];     // out_small

// ---------------- 1) fused reduce: block means + flat row-segment sums -----
// one block per (b,c) plane of 64x64. Reads x exactly once.
__global__ __launch_bounds__(256) void reduce_kernel(const float* __restrict__ x) {
    __shared__ float chunk[1024];   // sum of each 4-float chunk; f = h*16 + w/4
    int plane = blockIdx.x;         // b*512 + c
    const float4* xp = reinterpret_cast<const float4*>(x) + (size_t)plane * 1024;
    int t = threadIdx.x;
#pragma unroll
    for (int i = 0; i < 4; i++) {
        float4 v = xp[t + i * 256];
        chunk[t + i * 256] = v.x + v.y + v.z + v.w;
    }
    __syncthreads();
    // row-segment g = t: chunks 4t..4t+3 (same image row, 16 consecutive w)
    float rs = chunk[4 * t] + chunk[4 * t + 1] + chunk[4 * t + 2] + chunk[4 * t + 3];
    // block n = t: bh = t>>4, bw = t&15 -> chunks bh*64 + bw + {0,16,32,48}
    int base = ((t >> 4) << 6) + (t & 15);
    float bs = chunk[base] + chunk[base + 16] + chunk[base + 32] + chunk[base + 48];
    size_t o = (size_t)plane * NB + t;
    g_xrow[o] = rs;             // raw sum (V path)
    g_xavg[o] = bs * 0.0625f;   // mean over 16
}

// ---------------- 2) fused Q/K/Vsum GEMM ------------------------------------
// C[m,o] = sum_c A_T[c,m] * W[o,c] + bias[o]*bscale ; per batch M=256,N=512,K=512
__global__ __launch_bounds__(256) void gemm_qkv_kernel(
    const float* __restrict__ Wq, const float* __restrict__ bq,
    const float* __restrict__ Wk, const float* __restrict__ bk,
    const float* __restrict__ Wv, const float* __restrict__ bv) {
    int z = blockIdx.z;
    int b = z / 3, which = z - 3 * b;
    const float* A = (which == 2 ? g_xrow : g_xavg) + (size_t)b * CD * NB;
    const float* W;
    const float* bias;
    float* out;
    float bscale;
    if (which == 0)      { W = Wq; bias = bq; out = g_Q; bscale = 1.f; }
    else if (which == 1) { W = Wk; bias = bk; out = g_K; bscale = 1.f; }
    else                 { W = Wv; bias = bv; out = g_V; bscale = 16.f; }
    out += (size_t)b * NB * CD;

    int n0 = blockIdx.x * 128, m0 = blockIdx.y * 128;
    __shared__ float As[8][128];
    __shared__ float Bs[8][128];
    int t = threadIdx.x;
    int tx = t & 15, ty = t >> 4;
    int a_kk = t >> 5, a_mm = (t & 31) << 2;     // A tile load coords
    int b_nn = t >> 1, b_h = (t & 1) << 2;       // B tile load coords
    float acc[8][8] = {};

    for (int k0 = 0; k0 < CD; k0 += 8) {
        float4 av = *reinterpret_cast<const float4*>(&A[(size_t)(k0 + a_kk) * NB + m0 + a_mm]);
        float4 wv = *reinterpret_cast<const float4*>(&W[(size_t)(n0 + b_nn) * CD + k0 + b_h]);
        *reinterpret_cast<float4*>(&As[a_kk][a_mm]) = av;
        Bs[b_h + 0][b_nn] = wv.x;
        Bs[b_h + 1][b_nn] = wv.y;
        Bs[b_h + 2][b_nn] = wv.z;
        Bs[b_h + 3][b_nn] = wv.w;
        __syncthreads();
#pragma unroll
        for (int kk = 0; kk < 8; kk++) {
            float ra[8], rb[8];
#pragma unroll
            for (int i = 0; i < 8; i++) ra[i] = As[kk][ty * 8 + i];
#pragma unroll
            for (int j = 0; j < 8; j++) rb[j] = Bs[kk][tx * 8 + j];
#pragma unroll
            for (int i = 0; i < 8; i++)
#pragma unroll
                for (int j = 0; j < 8; j++) acc[i][j] += ra[i] * rb[j];
        }
        __syncthreads();
    }
#pragma unroll
    for (int i = 0; i < 8; i++) {
        int row = m0 + ty * 8 + i;
#pragma unroll
        for (int j = 0; j < 8; j += 4) {
            int col = n0 + tx * 8 + j;
            float4 v;
            v.x = acc[i][j]     + bias[col]     * bscale;
            v.y = acc[i][j + 1] + bias[col + 1] * bscale;
            v.z = acc[i][j + 2] + bias[col + 2] * bscale;
            v.w = acc[i][j + 3] + bias[col + 3] * bscale;
            *reinterpret_cast<float4*>(&out[(size_t)row * CD + col]) = v;
        }
    }
}

// ---------------- 3) scores: S = Q K^T / sqrt(C) ----------------------------
__global__ __launch_bounds__(256) void scores_kernel() {
    int b = blockIdx.z;
    int n0 = blockIdx.x * 64, m0 = blockIdx.y * 64;
    const float* Qb = g_Q + (size_t)b * NB * CD;
    const float* Kb = g_K + (size_t)b * NB * CD;
    __shared__ float Qs[16][68];
    __shared__ float Ks[16][68];
    int t = threadIdx.x;
    int row = t >> 2, kq = (t & 3) << 2;
    int tx = t & 15, ty = t >> 4;
    float acc[4][4] = {};

    for (int k0 = 0; k0 < CD; k0 += 16) {
        float4 q4 = *reinterpret_cast<const float4*>(&Qb[(size_t)(m0 + row) * CD + k0 + kq]);
        float4 k4 = *reinterpret_cast<const float4*>(&Kb[(size_t)(n0 + row) * CD + k0 + kq]);
        Qs[kq + 0][row] = q4.x; Qs[kq + 1][row] = q4.y;
        Qs[kq + 2][row] = q4.z; Qs[kq + 3][row] = q4.w;
        Ks[kq + 0][row] = k4.x; Ks[kq + 1][row] = k4.y;
        Ks[kq + 2][row] = k4.z; Ks[kq + 3][row] = k4.w;
        __syncthreads();
#pragma unroll
        for (int kk = 0; kk < 16; kk++) {
            float rq[4], rk[4];
#pragma unroll
            for (int i = 0; i < 4; i++) rq[i] = Qs[kk][ty * 4 + i];
#pragma unroll
            for (int j = 0; j < 4; j++) rk[j] = Ks[kk][tx * 4 + j];
#pragma unroll
            for (int i = 0; i < 4; i++)
#pragma unroll
                for (int j = 0; j < 4; j++) acc[i][j] += rq[i] * rk[j];
        }
        __syncthreads();
    }
    const float scale = 0.044194173824159216f;  // 1/sqrt(512)
    float* Sb = g_S + (size_t)b * NB * NB;
#pragma unroll
    for (int i = 0; i < 4; i++) {
        int r = m0 + ty * 4 + i;
        float4 v;
        v.x = acc[i][0] * scale; v.y = acc[i][1] * scale;
        v.z = acc[i][2] * scale; v.w = acc[i][3] * scale;
        *reinterpret_cast<float4*>(&Sb[(size_t)r * NB + n0 + tx * 4]) = v;
    }
}

// ---------------- 4) row softmax in place (one warp per row) ----------------
__global__ __launch_bounds__(256) void softmax_kernel() {
    int row = blockIdx.x * 8 + (threadIdx.x >> 5);
    int lane = threadIdx.x & 31;
    float* r = g_S + (size_t)row * NB;
    float v[8];
    float mx = -1e30f;
#pragma unroll
    for (int i = 0; i < 8; i++) {
        v[i] = r[lane + i * 32];
        mx = fmaxf(mx, v[i]);
    }
#pragma unroll
    for (int o = 16; o > 0; o >>= 1) mx = fmaxf(mx, __shfl_xor_sync(0xffffffffu, mx, o));
    float s = 0.f;
#pragma unroll
    for (int i = 0; i < 8; i++) { v[i] = __expf(v[i] - mx); s += v[i]; }
#pragma unroll
    for (int o = 16; o > 0; o >>= 1) s += __shfl_xor_sync(0xffffffffu, s, o);
    float inv = 1.0f / s;
#pragma unroll
    for (int i = 0; i < 8; i++) r[lane + i * 32] = v[i] * inv;
}

// ---------------- 5) out_small = A @ Vsum ------------------------------------
__global__ __launch_bounds__(256) void gemm_av_kernel() {
    int b = blockIdx.z;
    const float* A = g_S + (size_t)b * NB * NB;
    const float* Bm = g_V + (size_t)b * NB * CD;
    float* out = g_OS + (size_t)b * NB * CD;
    int n0 = blockIdx.x * 128, m0 = blockIdx.y * 128;
    __shared__ float As[8][128];
    __shared__ float Bs[8][128];
    int t = threadIdx.x;
    int tx = t & 15, ty = t >> 4;
    int a_mm = t >> 1, a_h = (t & 1) << 2;
    int b_kk = t >> 5, b_nn = (t & 31) << 2;
    float acc[8][8] = {};

    for (int k0 = 0; k0 < NB; k0 += 8) {
        float4 a4 = *reinterpret_cast<const float4*>(&A[(size_t)(m0 + a_mm) * NB + k0 + a_h]);
        float4 b4 = *reinterpret_cast<const float4*>(&Bm[(size_t)(k0 + b_kk) * CD + n0 + b_nn]);
        As[a_h + 0][a_mm] = a4.x;
        As[a_h + 1][a_mm] = a4.y;
        As[a_h + 2][a_mm] = a4.z;
        As[a_h + 3][a_mm] = a4.w;
        *reinterpret_cast<float4*>(&Bs[b_kk][b_nn]) = b4;
        __syncthreads();
#pragma unroll
        for (int kk = 0; kk < 8; kk++) {
            float ra[8], rb[8];
#pragma unroll
            for (int i = 0; i < 8; i++) ra[i] = As[kk][ty * 8 + i];
#pragma unroll
            for (int j = 0; j < 8; j++) rb[j] = Bs[kk][tx * 8 + j];
#pragma unroll
            for (int i = 0; i < 8; i++)
#pragma unroll
                for (int j = 0; j < 8; j++) acc[i][j] += ra[i] * rb[j];
        }
        __syncthreads();
    }
#pragma unroll
    for (int i = 0; i < 8; i++) {
        int row = m0 + ty * 8 + i;
#pragma unroll
        for (int j = 0; j < 8; j += 4) {
            int col = n0 + tx * 8 + j;
            float4 v;
            v.x = acc[i][j];
            v.y = acc[i][j + 1];
            v.z = acc[i][j + 2];
            v.w = acc[i][j + 3];
            *reinterpret_cast<float4*>(&out[(size_t)row * CD + col]) = v;
        }
    }
}

// ---------------- 6) scatter: broadcast each block row to 16 flat pixels ----
__global__ __launch_bounds__(1024) void scatter_kernel(float* __restrict__ out) {
    unsigned idx = blockIdx.x * 1024u + threadIdx.x;   // b,c,h,w flat
    unsigned b = idx >> 21;           // 512*4096 = 2^21
    unsigned rem = idx & 0x1FFFFFu;
    unsigned c = rem >> 12;           // /4096
    unsigned p = rem & 4095u;         // flat pixel
    unsigned n = p >> 4;              // flat group
    out[idx] = g_OS[((((b << 8) + n) << 9)) + c];
}

extern "C" void kernel_launch(void* const* d_in, const int* in_sizes, int n_in,
                              void* d_out, int out_size) {
    const float* x  = (const float*)d_in[0];
    const float* Wq = (const float*)d_in[1];
    const float* bq = (const float*)d_in[2];
    const float* Wk = (const float*)d_in[3];
    const float* bk = (const float*)d_in[4];
    const float* Wv = (const float*)d_in[5];
    const float* bv = (const float*)d_in[6];
    float* out = (float*)d_out;

    reduce_kernel<<<BATCH * CD, 256>>>(x);
    gemm_qkv_kernel<<<dim3(4, 2, BATCH * 3), 256>>>(Wq, bq, Wk, bk, Wv, bv);
    scores_kernel<<<dim3(4, 4, BATCH), 256>>>();
    softmax_kernel<<<BATCH * NB / 8, 256>>>();
    gemm_av_kernel<<<dim3(4, 2, BATCH), 256>>>();
    scatter_kernel<<<16384, 1024>>>(out);
}